// round 16
// baseline (speedup 1.0000x reference)
#include <cuda_runtime.h>

// RandomShiftsAug on GB300 — integer-shift copy with edge clamp.
// out[n,c,y,x] = in[n,c, clamp(y+sy-4,0,127), clamp(x+sx-4,0,127)]
//
// R16: 256-bit global ld/st (sm_100a+ .v8.b32 -> LDG.E.256/STG.E.256).
//  Warp = 4 rows of one (n,c) image; one v8 instruction covers 2 rows
//  (lane: rh=l>>4 selects row, oct=l&15 selects 8-float octet). Each warp
//  memory instruction spans 1024B contiguous -> better DRAM page locality.
//  X-shift via warp-uniform rot=sx&7 switch: each output word is one shfl
//  of a constant component from lane qa/qb. No smem, no barriers.

#define PADV 4
#define CB   9
#define HB   128
#define FULLM 0xFFFFFFFFu

// out[j] for rotation R: component (R+j)&7, from qa if R+j<8 else qb.
#define PK(R,J) __shfl_sync(FULLM, a[((R)+(J))&7], ((R)+(J)) < 8 ? qa : qb)
#define CASE8(R) case R: \
    o[0]=PK(R,0); o[1]=PK(R,1); o[2]=PK(R,2); o[3]=PK(R,3); \
    o[4]=PK(R,4); o[5]=PK(R,5); o[6]=PK(R,6); o[7]=PK(R,7); break;

__global__ void __launch_bounds__(256)
random_shift_v8_kernel(const float* __restrict__ x,
                       const int* __restrict__ shift,
                       float* __restrict__ out)
{
    int w = threadIdx.x >> 5;
    int l = threadIdx.x & 31;

    int gwarp = blockIdx.x * 8 + w;    // 147456 warps
    int grp   = gwarp & 31;            // 32 row-quartets per image
    int nc    = gwarp >> 5;            // n*9 + c
    int y0    = grp << 2;
    int n     = nc / CB;

    int sx = shift[2 * n]     - PADV;  // warp-uniform, in [-4,4]
    int sy = shift[2 * n + 1] - PADV;

    int rh  = l >> 4;                  // which of the 2 rows in a v8 step
    int oct = l & 15;                  // 8-float octet within the row

    const unsigned* __restrict__ img =
        reinterpret_cast<const unsigned*>(x) + nc * (HB * HB);

    // ---- 2 LDG.256 in flight: rows y0..y0+3 ----
    unsigned A[2][8];
    #pragma unroll
    for (int t = 0; t < 2; t++) {
        int ys = y0 + 2 * t + rh + sy;
        ys = ys < 0 ? 0 : (ys > HB - 1 ? HB - 1 : ys);
        const unsigned* p = img + ys * HB + (oct << 3);
        asm volatile("ld.global.cs.v8.b32 {%0,%1,%2,%3,%4,%5,%6,%7}, [%8];"
                     : "=r"(A[t][0]), "=r"(A[t][1]), "=r"(A[t][2]), "=r"(A[t][3]),
                       "=r"(A[t][4]), "=r"(A[t][5]), "=r"(A[t][6]), "=r"(A[t][7])
                     : "l"(p));
    }

    int c0 = (oct << 3) + sx;          // first source col of my output octet
    int q  = c0 >> 3;                  // source octet (arith shift = floor)
    int qa = rh * 16 + (q < 0 ? 0 : q);            // q <= 15 always here
    int qb = rh * 16 + (q + 1 > 15 ? 15 : q + 1);  // q+1 >= 0 always
    int rot = sx & 7;                  // warp-uniform (maps sx<0 to 8+sx)

    unsigned* __restrict__ dst =
        reinterpret_cast<unsigned*>(out) + (nc * HB + y0) * HB + (oct << 3);

    #pragma unroll
    for (int t = 0; t < 2; t++) {
        unsigned a[8];
        #pragma unroll
        for (int k = 0; k < 8; k++) a[k] = A[t][k];

        unsigned o[8];
        switch (rot) {                 // warp-uniform branch
            CASE8(0) CASE8(1) CASE8(2) CASE8(3)
            CASE8(4) CASE8(5) CASE8(6) CASE8(7)
        }

        // Edge clamp — warp-uniform guards; shfls are warp-wide inside.
        if (sx < 0) {                  // left edge: only oct==0 lanes clamp
            unsigned first = __shfl_sync(FULLM, a[0], rh * 16);       // col 0
            #pragma unroll
            for (int j = 0; j < 8; j++)
                if (c0 + j < 0) o[j] = first;
        } else if (sx > 0) {           // right edge: only oct==15 lanes clamp
            unsigned last = __shfl_sync(FULLM, a[7], rh * 16 + 15);   // col 127
            #pragma unroll
            for (int j = 0; j < 8; j++)
                if (c0 + j > HB - 1) o[j] = last;
        }

        unsigned* d = dst + (2 * t + rh) * HB;
        asm volatile("st.global.cs.v8.b32 [%0], {%1,%2,%3,%4,%5,%6,%7,%8};"
                     :: "l"(d), "r"(o[0]), "r"(o[1]), "r"(o[2]), "r"(o[3]),
                        "r"(o[4]), "r"(o[5]), "r"(o[6]), "r"(o[7])
                     : "memory");
    }
}

extern "C" void kernel_launch(void* const* d_in, const int* in_sizes, int n_in,
                              void* d_out, int out_size)
{
    const float* x     = (const float*)d_in[0];
    const int*   shift = (const int*)d_in[1];
    float*       out   = (float*)d_out;

    // 4608 images * 32 row-quartets = 147456 warps / 8 per CTA = 18432 CTAs
    random_shift_v8_kernel<<<18432, 256>>>(x, shift, out);
}